// round 1
// baseline (speedup 1.0000x reference)
#include <cuda_runtime.h>
#include <cstdint>

#define NODES 50
#define EPG   400
#define NGRAPH 512
#define NN    (NGRAPH*NODES)   // 25600
#define NE    (NGRAPH*EPG)     // 204800
#define FDIM  512
#define HEADS 8
#define CH    64
#define NA    5
#define GRUH  128
#define GRUI  1024
#define G3    384

// ---------------- scratch (static device globals; no allocation) ----------------
__device__ float g_bufA[NN*FDIM];
__device__ float g_bufB[NN*FDIM];
__device__ float g_gemb[NGRAPH*FDIM];
__device__ float g_comb[NGRAPH*NA*GRUI];
__device__ float g_GI[NGRAPH*NA*G3];
__device__ float g_GHbuf[NGRAPH*G3];
__device__ float g_h0[NGRAPH*GRUH];
__device__ float g_h1[NGRAPH*GRUH];
__device__ float g_gruout[NGRAPH*NA*GRUH];

// ---------------- x @ W1  (K=4) ----------------
__global__ void lin1_k(const float* __restrict__ x, const float* __restrict__ W,
                       float* __restrict__ out) {
    int idx = blockIdx.x * 256 + threadIdx.x;     // NN*FDIM threads
    int n = idx >> 9, f = idx & 511;
    const float* xr = x + n * 4;
    float acc = xr[0]*W[f] + xr[1]*W[512+f] + xr[2]*W[1024+f] + xr[3]*W[1536+f];
    out[idx] = acc;
}

// ---------------- generic fp32 sgemm: C[M,N] = A[M,K] * B[K,N] ----------------
// M%128==0, N%128==0, K%8==0
__global__ void __launch_bounds__(256) sgemm128(
    const float* __restrict__ A, const float* __restrict__ B,
    float* __restrict__ C, int M, int N, int K) {
    __shared__ float As[8][128];
    __shared__ float Bs[8][128];
    const int tid = threadIdx.x;
    const int bm = blockIdx.y * 128, bn = blockIdx.x * 128;
    const int arow = tid >> 1, acol = (tid & 1) << 2;
    const int brow = tid >> 5, bcol = (tid & 31) << 2;
    const int tr = (tid >> 4) << 3, tc = (tid & 15) << 3;
    float acc[8][8];
#pragma unroll
    for (int i = 0; i < 8; i++)
#pragma unroll
        for (int j = 0; j < 8; j++) acc[i][j] = 0.f;
    const float* Aptr = A + (size_t)(bm + arow) * K + acol;
    const float* Bptr = B + (size_t)brow * N + bn + bcol;
    for (int k0 = 0; k0 < K; k0 += 8) {
        float4 a4 = *(const float4*)(Aptr + k0);
        As[acol + 0][arow] = a4.x; As[acol + 1][arow] = a4.y;
        As[acol + 2][arow] = a4.z; As[acol + 3][arow] = a4.w;
        float4 b4 = *(const float4*)(Bptr + (size_t)k0 * N);
        *(float4*)&Bs[brow][bcol] = b4;
        __syncthreads();
#pragma unroll
        for (int k = 0; k < 8; k++) {
            float ar[8], br[8];
#pragma unroll
            for (int i = 0; i < 8; i++) ar[i] = As[k][tr + i];
#pragma unroll
            for (int j = 0; j < 8; j++) br[j] = Bs[k][tc + j];
#pragma unroll
            for (int i = 0; i < 8; i++)
#pragma unroll
                for (int j = 0; j < 8; j++) acc[i][j] += ar[i] * br[j];
        }
        __syncthreads();
    }
#pragma unroll
    for (int i = 0; i < 8; i++) {
        float4* cp = (float4*)&C[(size_t)(bm + tr + i) * N + bn + tc];
        cp[0] = make_float4(acc[i][0], acc[i][1], acc[i][2], acc[i][3]);
        cp[1] = make_float4(acc[i][4], acc[i][5], acc[i][6], acc[i][7]);
    }
}

// ---------------- per-graph GAT layer (whole graph resident in smem) ----------------
// smem word layout (floats unless noted):
//   h[50*512] | ssrc[400] | sdst[400] | alS[450*8] | den[400] | av[1024] | weae[8]
//   | easum[50] | (int) amaxi[400] | srcS[450] | dstS[450] | cnt[50] | off[50] | cur[50]
#define GAT_SMEM_WORDS (25600+400+400+3600+400+1024+8+50+400+450+450+50+50+50)
#define GAT_SMEM_BYTES (GAT_SMEM_WORDS*4)

template <bool LOOPS>
__global__ void __launch_bounds__(512) gat_kernel(
    const float* __restrict__ hpre,
    const int* __restrict__ esrc, const int* __restrict__ edst,
    const float* __restrict__ ea,
    const float* __restrict__ a_src, const float* __restrict__ a_dst,
    const float* __restrict__ We, const float* __restrict__ ae,
    const float* __restrict__ bias, float* __restrict__ xout) {
    extern __shared__ float sm[];
    float* sh_h     = sm;                    // 25600
    float* sh_ssrc  = sm + 25600;            // 400
    float* sh_sdst  = sh_ssrc + 400;         // 400
    float* sh_alS   = sh_sdst + 400;         // 3600
    float* sh_den   = sh_alS + 3600;         // 400
    float* sh_av    = sh_den + 400;          // 1024
    float* sh_weae  = sh_av + 1024;          // 8
    float* sh_easum = sh_weae + 8;           // 50
    int*   sh_amaxi = (int*)(sh_easum + 50); // 400
    int*   sh_srcS  = sh_amaxi + 400;        // 450
    int*   sh_dstS  = sh_srcS + 450;         // 450
    int*   sh_cnt   = sh_dstS + 450;         // 50
    int*   sh_off   = sh_cnt + 50;           // 50
    int*   sh_cur   = sh_off + 50;           // 50

    const int g = blockIdx.x;
    const int nb = g * NODES;
    const int eb = g * EPG;
    const int tid = threadIdx.x;
    const int lane = tid & 31, wid = tid >> 5;
    const int ECNT = LOOPS ? (EPG + NODES) : EPG;

    // phase 0a: init + load attention vectors + edge-feature constants
    if (tid < 400) { sh_den[tid] = 0.f; sh_amaxi[tid] = 0; }
    if (tid < NODES) { sh_cnt[tid] = 0; sh_easum[tid] = 0.f; sh_cur[tid] = 0; }
    sh_av[tid] = a_src[tid];
    sh_av[512 + tid] = a_dst[tid];
    if (tid < 8) {
        float s = 0.f;
#pragma unroll
        for (int c = 0; c < 64; c++) s += We[tid * 64 + c] * ae[tid * 64 + c];
        sh_weae[tid] = s;
    }
    __syncthreads();

    // phase 0b: load node features; count incoming edges + edge-attr sums
    {
        const float4* s4 = (const float4*)(hpre + (size_t)nb * FDIM);
        float4* d4 = (float4*)sh_h;
        for (int i = tid; i < NODES * FDIM / 4; i += 512) d4[i] = s4[i];
    }
    for (int e = tid; e < EPG; e += 512) {
        int d = edst[eb + e] - nb;
        atomicAdd(&sh_cnt[d], 1);
        atomicAdd(&sh_easum[d], ea[eb + e]);
    }
    __syncthreads();

    // phase 1: per-(node,head) src/dst attention scores (warp per pair)
    for (int p = wid; p < NODES * HEADS; p += 16) {
        int n = p >> 3, h = p & 7;
        const float* hr = sh_h + n * FDIM + h * CH;
        float v0 = hr[lane], v1 = hr[lane + 32];
        float s1 = v0 * sh_av[h * CH + lane] + v1 * sh_av[h * CH + lane + 32];
        float s2 = v0 * sh_av[512 + h * CH + lane] + v1 * sh_av[512 + h * CH + lane + 32];
#pragma unroll
        for (int o = 16; o > 0; o >>= 1) {
            s1 += __shfl_xor_sync(0xffffffffu, s1, o);
            s2 += __shfl_xor_sync(0xffffffffu, s2, o);
        }
        if (lane == 0) { sh_ssrc[p] = s1; sh_sdst[p] = s2; }
    }
    __syncthreads();

    // phase 2: exclusive scan of per-dst counts
    if (tid == 0) {
        int o = 0;
        for (int n = 0; n < NODES; n++) { sh_off[n] = o; o += sh_cnt[n] + (LOOPS ? 1 : 0); }
    }
    __syncthreads();

    // phase 3: attention logits (leaky-relu) written in dst-sorted order + running max
    for (int e = tid; e < ECNT; e += 512) {
        int sl, dl; float eav;
        if (e < EPG) { sl = esrc[eb + e] - nb; dl = edst[eb + e] - nb; eav = ea[eb + e]; }
        else { sl = dl = e - EPG; eav = sh_easum[dl] / fmaxf((float)sh_cnt[dl], 1.f); }
        int pos = sh_off[dl] + atomicAdd(&sh_cur[dl], 1);
        sh_srcS[pos] = sl; sh_dstS[pos] = dl;
#pragma unroll
        for (int h = 0; h < 8; h++) {
            float al = sh_ssrc[sl * 8 + h] + sh_sdst[dl * 8 + h] + eav * sh_weae[h];
            al = al > 0.f ? al : 0.2f * al;
            sh_alS[pos * 8 + h] = al;
            // max(0, max al): float-as-int atomicMax is exact for the >=0 winner
            atomicMax(&sh_amaxi[dl * 8 + h], __float_as_int(al));
        }
    }
    __syncthreads();

    // phase 4: exp + denom
    for (int i = tid; i < ECNT; i += 512) {
        int dl = sh_dstS[i];
#pragma unroll
        for (int h = 0; h < 8; h++) {
            float p = expf(sh_alS[i * 8 + h] - __int_as_float(sh_amaxi[dl * 8 + h]));
            sh_alS[i * 8 + h] = p;
            atomicAdd(&sh_den[dl * 8 + h], p);
        }
    }
    __syncthreads();
    if (tid < 400) sh_den[tid] = 1.f / (sh_den[tid] + 1e-16f);
    __syncthreads();

    // phase 5: aggregation (warp per node, lane covers 16 channels), + bias + relu
    for (int n = wid; n < NODES; n += 16) {
        float acc[16];
#pragma unroll
        for (int k = 0; k < 16; k++) acc[k] = 0.f;
        const int beg = sh_off[n], end = beg + sh_cur[n];
        for (int j = beg; j < end; j++) {
            const int s = sh_srcS[j];
            const float* hs = sh_h + s * FDIM;
            float alpha[8];
#pragma unroll
            for (int h = 0; h < 8; h++) alpha[h] = sh_alS[j * 8 + h] * sh_den[n * 8 + h];
#pragma unroll
            for (int k = 0; k < 16; k++) {
                int f = lane + (k << 5);
                acc[k] += alpha[k >> 1] * hs[f];
            }
        }
#pragma unroll
        for (int k = 0; k < 16; k++) {
            int f = lane + (k << 5);
            float v = acc[k] + bias[f];
            xout[(size_t)(nb + n) * FDIM + f] = v > 0.f ? v : 0.f;
        }
    }
}

// ---------------- mean pool over 50 nodes per graph ----------------
__global__ void pool_k(const float* __restrict__ x3, float* __restrict__ gemb) {
    int b = blockIdx.x;
    int f = blockIdx.y * 128 + threadIdx.x;
    float s = 0.f;
#pragma unroll 10
    for (int n = 0; n < NODES; n++) s += x3[(size_t)(b * NODES + n) * FDIM + f];
    gemb[b * FDIM + f] = s * (1.f / 50.f);
}

// ---------------- build combined [B*5, 1024] = [agent_emb | graph_emb] ----------------
__global__ void gather_k(const float* __restrict__ x3, const float* __restrict__ gemb,
                         float* __restrict__ comb) {
    int r = blockIdx.x;        // b*5 + t
    int b = r / 5, t = r - b * 5;
    for (int i = threadIdx.x; i < GRUI; i += 256)
        comb[(size_t)r * GRUI + i] =
            (i < 512) ? x3[(size_t)(b * NODES + t) * FDIM + i] : gemb[b * FDIM + i - 512];
}

// ---------------- GRU: GH = h @ Whh  (M=512, K=128, N=384) ----------------
__global__ void gru_gh_k(const float* __restrict__ h, const float* __restrict__ Whh,
                         float* __restrict__ GH) {
    __shared__ float hs[8 * GRUH];
    int b0 = blockIdx.x * 8;
    int tid = threadIdx.x;   // 384
    for (int i = tid; i < 8 * GRUH; i += 384) hs[i] = h[b0 * GRUH + i];
    __syncthreads();
    float acc[8];
#pragma unroll
    for (int r = 0; r < 8; r++) acc[r] = 0.f;
    for (int k = 0; k < GRUH; k++) {
        float w = Whh[k * G3 + tid];
#pragma unroll
        for (int r = 0; r < 8; r++) acc[r] += hs[r * GRUH + k] * w;
    }
#pragma unroll
    for (int r = 0; r < 8; r++) GH[(b0 + r) * G3 + tid] = acc[r];
}

// ---------------- GRU gate math ----------------
__global__ void gru_gate_k(const float* __restrict__ GI, int t,
                           const float* __restrict__ GHb, const float* __restrict__ hprev,
                           const float* __restrict__ bih, const float* __restrict__ bhh,
                           float* __restrict__ hnew, float* __restrict__ gout,
                           float* __restrict__ hlast) {
    int b = blockIdx.x, j = threadIdx.x;
    const float* gi = GI + (size_t)(b * NA + t) * G3;
    const float* gh = GHb + (size_t)b * G3;
    float ir = gi[j] + bih[j];
    float iz = gi[j + 128] + bih[j + 128];
    float in_ = gi[j + 256] + bih[j + 256];
    float hr = gh[j] + bhh[j];
    float hz = gh[j + 128] + bhh[j + 128];
    float hn = gh[j + 256] + bhh[j + 256];
    float r = 1.f / (1.f + expf(-(ir + hr)));
    float z = 1.f / (1.f + expf(-(iz + hz)));
    float nn = tanhf(in_ + r * hn);
    float hp = hprev[b * GRUH + j];
    float h = (1.f - z) * nn + z * hp;
    hnew[b * GRUH + j] = h;
    gout[(size_t)(b * NA + t) * GRUH + j] = h;
    if (hlast) hlast[b * GRUH + j] = h;
}

// ---------------- FC head: relu(g@fc1+b) @ fc2 + b, and action_std ----------------
__global__ void fc_k(const float* __restrict__ gout, const float* __restrict__ W1,
                     const float* __restrict__ b1, const float* __restrict__ W2,
                     const float* __restrict__ b2, const float* __restrict__ ls,
                     float* __restrict__ out) {
    __shared__ float g[128];
    __shared__ float f1[64];
    int r = blockIdx.x, tid = threadIdx.x;  // 64 threads
    g[tid] = gout[(size_t)r * GRUH + tid];
    g[tid + 64] = gout[(size_t)r * GRUH + tid + 64];
    __syncthreads();
    float acc = b1[tid];
#pragma unroll 8
    for (int k = 0; k < 128; k++) acc += g[k] * W1[k * 64 + tid];
    f1[tid] = acc > 0.f ? acc : 0.f;
    __syncthreads();
    if (tid < 3) {
        float a2 = b2[tid];
#pragma unroll
        for (int k = 0; k < 64; k++) a2 += f1[k] * W2[k * 3 + tid];
        out[r * 3 + tid] = a2;                                 // action_mean
        float l = ls[tid];
        l = fminf(fmaxf(l, -20.f), 2.f);
        out[NGRAPH * NA * 3 + r * 3 + tid] = expf(l);          // action_std
    }
}

// ---------------- launch ----------------
extern "C" void kernel_launch(void* const* d_in, const int* in_sizes, int n_in,
                              void* d_out, int out_size) {
    const float* x      = (const float*)d_in[0];
    const int*   ei     = (const int*)d_in[1];
    const float* ea     = (const float*)d_in[2];
    const float* hid0   = (const float*)d_in[3];
    const float* W1     = (const float*)d_in[4];
    const float* a_s1   = (const float*)d_in[5];
    const float* a_d1   = (const float*)d_in[6];
    const float* We1    = (const float*)d_in[7];
    const float* ae1    = (const float*)d_in[8];
    const float* b1     = (const float*)d_in[9];
    const float* W2     = (const float*)d_in[10];
    const float* a_s2   = (const float*)d_in[11];
    const float* a_d2   = (const float*)d_in[12];
    const float* We2    = (const float*)d_in[13];
    const float* ae2    = (const float*)d_in[14];
    const float* b2     = (const float*)d_in[15];
    const float* W3     = (const float*)d_in[16];
    const float* a_s3   = (const float*)d_in[17];
    const float* a_d3   = (const float*)d_in[18];
    const float* We3    = (const float*)d_in[19];
    const float* ae3    = (const float*)d_in[20];
    const float* b3     = (const float*)d_in[21];
    const float* Wih    = (const float*)d_in[22];
    const float* Whh    = (const float*)d_in[23];
    const float* bih    = (const float*)d_in[24];
    const float* bhh    = (const float*)d_in[25];
    const float* fc1W   = (const float*)d_in[26];
    const float* fc1b   = (const float*)d_in[27];
    const float* fc2W   = (const float*)d_in[28];
    const float* fc2b   = (const float*)d_in[29];
    const float* logstd = (const float*)d_in[30];
    float* out = (float*)d_out;

    float *bufA, *bufB, *gemb, *comb, *GI, *GHb, *h0b, *h1b, *gout;
    cudaGetSymbolAddress((void**)&bufA, g_bufA);
    cudaGetSymbolAddress((void**)&bufB, g_bufB);
    cudaGetSymbolAddress((void**)&gemb, g_gemb);
    cudaGetSymbolAddress((void**)&comb, g_comb);
    cudaGetSymbolAddress((void**)&GI,   g_GI);
    cudaGetSymbolAddress((void**)&GHb,  g_GHbuf);
    cudaGetSymbolAddress((void**)&h0b,  g_h0);
    cudaGetSymbolAddress((void**)&h1b,  g_h1);
    cudaGetSymbolAddress((void**)&gout, g_gruout);

    cudaFuncSetAttribute(gat_kernel<false>, cudaFuncAttributeMaxDynamicSharedMemorySize, GAT_SMEM_BYTES);
    cudaFuncSetAttribute(gat_kernel<true>,  cudaFuncAttributeMaxDynamicSharedMemorySize, GAT_SMEM_BYTES);

    const int* esrc = ei;
    const int* edst = ei + NE;

    // layer 1
    lin1_k<<<(NN * FDIM) / 256, 256>>>(x, W1, bufA);
    gat_kernel<false><<<NGRAPH, 512, GAT_SMEM_BYTES>>>(bufA, esrc, edst, ea,
                                                       a_s1, a_d1, We1, ae1, b1, bufB);
    // layer 2
    sgemm128<<<dim3(FDIM / 128, NN / 128), 256>>>(bufB, W2, bufA, NN, FDIM, FDIM);
    gat_kernel<true><<<NGRAPH, 512, GAT_SMEM_BYTES>>>(bufA, esrc, edst, ea,
                                                      a_s2, a_d2, We2, ae2, b2, bufB);
    // layer 3
    sgemm128<<<dim3(FDIM / 128, NN / 128), 256>>>(bufB, W3, bufA, NN, FDIM, FDIM);
    gat_kernel<true><<<NGRAPH, 512, GAT_SMEM_BYTES>>>(bufA, esrc, edst, ea,
                                                      a_s3, a_d3, We3, ae3, b3, bufB);
    // pooling + GRU input
    pool_k<<<dim3(NGRAPH, FDIM / 128), 128>>>(bufB, gemb);
    gather_k<<<NGRAPH * NA, 256>>>(bufB, gemb, comb);
    sgemm128<<<dim3(G3 / 128, (NGRAPH * NA) / 128), 256>>>(comb, Wih, GI,
                                                           NGRAPH * NA, G3, GRUI);
    // GRU recurrence
    cudaMemcpyAsync(h0b, hid0, (size_t)NGRAPH * GRUH * sizeof(float),
                    cudaMemcpyDeviceToDevice);
    for (int t = 0; t < NA; t++) {
        float* hc = (t & 1) ? h1b : h0b;
        float* hn = (t & 1) ? h0b : h1b;
        gru_gh_k<<<NGRAPH / 8, G3>>>(hc, Whh, GHb);
        gru_gate_k<<<NGRAPH, GRUH>>>(GI, t, GHb, hc, bih, bhh, hn, gout,
                                     (t == NA - 1) ? (out + NGRAPH * NA * 3 * 2) : nullptr);
    }
    // FC head -> action_mean, action_std
    fc_k<<<NGRAPH * NA, 64>>>(gout, fc1W, fc1b, fc2W, fc2b, logstd, out);
}

// round 4
// speedup vs baseline: 1.6060x; 1.6060x over previous
#include <cuda_runtime.h>
#include <cuda_bf16.h>
#include <cstdint>

#define NODES 50
#define EPG   400
#define NGRAPH 512
#define NN    (NGRAPH*NODES)   // 25600
#define NE    (NGRAPH*EPG)     // 204800
#define FDIM  512
#define HEADS 8
#define CH    64
#define NA    5
#define GRUH  128
#define GRUI  1024
#define G3    384

// ---------------- scratch (static device globals; no allocation) ----------------
__device__ float g_bufA[NN*FDIM];
__device__ float g_bufB[NN*FDIM];
__device__ __nv_bfloat16 g_Ah[NN*FDIM];
__device__ __nv_bfloat16 g_Al[NN*FDIM];
__device__ __nv_bfloat16 g_Bh[GRUI*G3 > FDIM*FDIM ? GRUI*G3 : FDIM*FDIM];
__device__ __nv_bfloat16 g_Bl[GRUI*G3 > FDIM*FDIM ? GRUI*G3 : FDIM*FDIM];
__device__ float g_gemb[NGRAPH*FDIM];
__device__ float g_comb[NGRAPH*NA*GRUI];
__device__ float g_GI[NGRAPH*NA*G3];
__device__ float g_GHbuf[NGRAPH*G3];
__device__ float g_h0[NGRAPH*GRUH];
__device__ float g_h1[NGRAPH*GRUH];
__device__ float g_gruout[NGRAPH*NA*GRUH];

// ---------------- helpers ----------------
__device__ __forceinline__ uint32_t smem_u32(const void* p) {
    uint32_t a;
    asm("{ .reg .u64 t; cvta.to.shared.u64 t, %1; cvt.u32.u64 %0, t; }" : "=r"(a) : "l"(p));
    return a;
}
__device__ __forceinline__ void cp16(uint32_t sdst, const void* gsrc) {
    asm volatile("cp.async.cg.shared.global [%0], [%1], 16;" :: "r"(sdst), "l"(gsrc) : "memory");
}
__device__ __forceinline__ uint32_t lds32(uint32_t a) {
    uint32_t v;
    asm volatile("ld.shared.b32 %0, [%1];" : "=r"(v) : "r"(a));
    return v;
}
__device__ __forceinline__ void mma16816(float* c, uint32_t a0, uint32_t a1,
                                         uint32_t a2, uint32_t a3,
                                         uint32_t b0, uint32_t b1) {
    asm volatile(
        "mma.sync.aligned.m16n8k16.row.col.f32.bf16.bf16.f32 "
        "{%0,%1,%2,%3}, {%4,%5,%6,%7}, {%8,%9}, {%0,%1,%2,%3};"
        : "+f"(c[0]), "+f"(c[1]), "+f"(c[2]), "+f"(c[3])
        : "r"(a0), "r"(a1), "r"(a2), "r"(a3), "r"(b0), "r"(b1));
}

// ---------------- fp32 -> bf16 hi/lo split ----------------
__global__ void split_k(const float* __restrict__ in, __nv_bfloat16* __restrict__ hi,
                        __nv_bfloat16* __restrict__ lo, int n4) {
    int i = blockIdx.x * 256 + threadIdx.x;
    if (i >= n4) return;
    float4 v = ((const float4*)in)[i];
    __nv_bfloat16 h0 = __float2bfloat16_rn(v.x);
    __nv_bfloat16 h1 = __float2bfloat16_rn(v.y);
    __nv_bfloat16 h2 = __float2bfloat16_rn(v.z);
    __nv_bfloat16 h3 = __float2bfloat16_rn(v.w);
    __nv_bfloat16 l0 = __float2bfloat16_rn(v.x - __bfloat162float(h0));
    __nv_bfloat16 l1 = __float2bfloat16_rn(v.y - __bfloat162float(h1));
    __nv_bfloat16 l2 = __float2bfloat16_rn(v.z - __bfloat162float(h2));
    __nv_bfloat16 l3 = __float2bfloat16_rn(v.w - __bfloat162float(h3));
    ((__nv_bfloat162*)hi)[i*2]   = __nv_bfloat162(h0, h1);
    ((__nv_bfloat162*)hi)[i*2+1] = __nv_bfloat162(h2, h3);
    ((__nv_bfloat162*)lo)[i*2]   = __nv_bfloat162(l0, l1);
    ((__nv_bfloat162*)lo)[i*2+1] = __nv_bfloat162(l2, l3);
}

// W [K,N] fp32 -> Wt [N,K] bf16 hi/lo (transposed)
__global__ void splitT_k(const float* __restrict__ W, __nv_bfloat16* __restrict__ hi,
                         __nv_bfloat16* __restrict__ lo, int K, int N) {
    int idx = blockIdx.x * 256 + threadIdx.x;
    if (idx >= N * K) return;
    int n = idx / K, k = idx - n * K;
    float v = W[(size_t)k * N + n];
    __nv_bfloat16 h = __float2bfloat16_rn(v);
    hi[idx] = h;
    lo[idx] = __float2bfloat16_rn(v - __bfloat162float(h));
}

// ---------------- HMMA bf16-split GEMM: C[M,N] = A[M,K] * B[N,K]^T ----------------
// CTA tile 128x128, 8 warps (4x2), warp tile 32x64, K-chunk 32, 3-stage cp.async.
#define STAGES 3
#define PITCH 80                       // bytes per 32-bf16 smem row (conflict-free)
#define MAT_BYTES (128*PITCH)          // 10240
#define STAGE_BYTES (4*MAT_BYTES)      // Ah|Al|Bh|Bl
#define GEMM_SMEM (STAGES*STAGE_BYTES) // 122880

__global__ void __launch_bounds__(256) gemm_mma(
    const __nv_bfloat16* __restrict__ Ah, const __nv_bfloat16* __restrict__ Al,
    const __nv_bfloat16* __restrict__ Bh, const __nv_bfloat16* __restrict__ Bl,
    float* __restrict__ C, int M, int N, int K) {
    extern __shared__ char sm8[];
    const uint32_t sb = smem_u32(sm8);
    const int tid = threadIdx.x;
    const int lane = tid & 31, wid = tid >> 5;
    const int wm = wid & 3, wn = wid >> 2;     // 4x2 warp grid
    const int bm = blockIdx.y * 128, bn = blockIdx.x * 128;
    const int g = lane >> 2, tig = lane & 3;
    const int NCH = K >> 5;

    const char* pAh = (const char*)Ah;
    const char* pAl = (const char*)Al;
    const char* pBh = (const char*)Bh;
    const char* pBl = (const char*)Bl;
    const size_t rowb = (size_t)K * 2;

    auto load_stage = [&](int kc, int s) {
        uint32_t sbase = sb + s * STAGE_BYTES;
        size_t kb = (size_t)kc * 64;
#pragma unroll
        for (int i = tid; i < 512; i += 256) {
            int r = i >> 2, gg = i & 3;
            uint32_t so = sbase + r * PITCH + gg * 16;
            size_t ga = (size_t)(bm + r) * rowb + kb + gg * 16;
            size_t gb = (size_t)(bn + r) * rowb + kb + gg * 16;
            cp16(so,                 pAh + ga);
            cp16(so + MAT_BYTES,     pAl + ga);
            cp16(so + 2*MAT_BYTES,   pBh + gb);
            cp16(so + 3*MAT_BYTES,   pBl + gb);
        }
        asm volatile("cp.async.commit_group;" ::: "memory");
    };

    float acc[2][8][4];
#pragma unroll
    for (int f = 0; f < 2; f++)
#pragma unroll
        for (int nf = 0; nf < 8; nf++)
#pragma unroll
            for (int c = 0; c < 4; c++) acc[f][nf][c] = 0.f;

    load_stage(0, 0);
    load_stage(1, 1);

    for (int kc = 0; kc < NCH; kc++) {
        int s = kc % STAGES;
        asm volatile("cp.async.wait_group 1;" ::: "memory");
        __syncthreads();
        // prefetch next-next chunk
        if (kc + 2 < NCH) load_stage(kc + 2, (kc + 2) % STAGES);
        else asm volatile("cp.async.commit_group;" ::: "memory");

        uint32_t aA = sb + s * STAGE_BYTES;
        uint32_t aB = aA + 2*MAT_BYTES;
#pragma unroll
        for (int kk = 0; kk < 2; kk++) {       // two k16 steps
            const uint32_t kof = kk * 32 + tig * 4;
            uint32_t ah[2][4], al[2][4];
#pragma unroll
            for (int f = 0; f < 2; f++) {
                uint32_t r0 = (uint32_t)(wm * 32 + f * 16 + g) * PITCH + kof;
                ah[f][0] = lds32(aA + r0);
                ah[f][1] = lds32(aA + r0 + 8*PITCH);
                ah[f][2] = lds32(aA + r0 + 16);
                ah[f][3] = lds32(aA + r0 + 8*PITCH + 16);
                al[f][0] = lds32(aA + MAT_BYTES + r0);
                al[f][1] = lds32(aA + MAT_BYTES + r0 + 8*PITCH);
                al[f][2] = lds32(aA + MAT_BYTES + r0 + 16);
                al[f][3] = lds32(aA + MAT_BYTES + r0 + 8*PITCH + 16);
            }
#pragma unroll
            for (int nf = 0; nf < 8; nf++) {
                uint32_t n0 = (uint32_t)(wn * 64 + nf * 8 + g) * PITCH + kof;
                uint32_t bh0 = lds32(aB + n0);
                uint32_t bh1 = lds32(aB + n0 + 16);
                uint32_t bl0 = lds32(aB + MAT_BYTES + n0);
                uint32_t bl1 = lds32(aB + MAT_BYTES + n0 + 16);
#pragma unroll
                for (int f = 0; f < 2; f++) {
                    mma16816(acc[f][nf], ah[f][0], ah[f][1], ah[f][2], ah[f][3], bh0, bh1);
                    mma16816(acc[f][nf], ah[f][0], ah[f][1], ah[f][2], ah[f][3], bl0, bl1);
                    mma16816(acc[f][nf], al[f][0], al[f][1], al[f][2], al[f][3], bh0, bh1);
                }
            }
        }
        __syncthreads();
    }

    // epilogue: fp32 stores (float2 per fragment row)
#pragma unroll
    for (int f = 0; f < 2; f++) {
        int r0 = bm + wm * 32 + f * 16 + g;
#pragma unroll
        for (int nf = 0; nf < 8; nf++) {
            int c0 = bn + wn * 64 + nf * 8 + 2 * tig;
            *(float2*)&C[(size_t)r0 * N + c0]       = make_float2(acc[f][nf][0], acc[f][nf][1]);
            *(float2*)&C[(size_t)(r0 + 8) * N + c0] = make_float2(acc[f][nf][2], acc[f][nf][3]);
        }
    }
}

// ---------------- x @ W1  (K=4) ----------------
__global__ void lin1_k(const float* __restrict__ x, const float* __restrict__ W,
                       float* __restrict__ out) {
    int idx = blockIdx.x * 256 + threadIdx.x;
    int n = idx >> 9, f = idx & 511;
    const float* xr = x + n * 4;
    out[idx] = xr[0]*W[f] + xr[1]*W[512+f] + xr[2]*W[1024+f] + xr[3]*W[1536+f];
}

// ---------------- per-graph GAT layer ----------------
#define GAT_SMEM_WORDS (25600+400+400+3600+400+1024+8+50+400+450+450+50+50+50)
#define GAT_SMEM_BYTES (GAT_SMEM_WORDS*4)

template <bool LOOPS>
__global__ void __launch_bounds__(512) gat_kernel(
    const float* __restrict__ hpre,
    const int* __restrict__ esrc, const int* __restrict__ edst,
    const float* __restrict__ ea,
    const float* __restrict__ a_src, const float* __restrict__ a_dst,
    const float* __restrict__ We, const float* __restrict__ ae,
    const float* __restrict__ bias, float* __restrict__ xout) {
    extern __shared__ float sm[];
    float* sh_h     = sm;
    float* sh_ssrc  = sm + 25600;
    float* sh_sdst  = sh_ssrc + 400;
    float* sh_alS   = sh_sdst + 400;
    float* sh_den   = sh_alS + 3600;
    float* sh_av    = sh_den + 400;
    float* sh_weae  = sh_av + 1024;
    float* sh_easum = sh_weae + 8;
    int*   sh_amaxi = (int*)(sh_easum + 50);
    int*   sh_srcS  = sh_amaxi + 400;
    int*   sh_dstS  = sh_srcS + 450;
    int*   sh_cnt   = sh_dstS + 450;
    int*   sh_off   = sh_cnt + 50;
    int*   sh_cur   = sh_off + 50;

    const int g = blockIdx.x;
    const int nb = g * NODES;
    const int eb = g * EPG;
    const int tid = threadIdx.x;
    const int lane = tid & 31, wid = tid >> 5;
    const int ECNT = LOOPS ? (EPG + NODES) : EPG;

    if (tid < 400) { sh_den[tid] = 0.f; sh_amaxi[tid] = 0; }
    if (tid < NODES) { sh_cnt[tid] = 0; sh_easum[tid] = 0.f; sh_cur[tid] = 0; }
    sh_av[tid] = a_src[tid];
    sh_av[512 + tid] = a_dst[tid];
    if (tid < 8) {
        float s = 0.f;
#pragma unroll
        for (int c = 0; c < 64; c++) s += We[tid * 64 + c] * ae[tid * 64 + c];
        sh_weae[tid] = s;
    }
    __syncthreads();

    {
        const float4* s4 = (const float4*)(hpre + (size_t)nb * FDIM);
        float4* d4 = (float4*)sh_h;
        for (int i = tid; i < NODES * FDIM / 4; i += 512) d4[i] = s4[i];
    }
    for (int e = tid; e < EPG; e += 512) {
        int d = edst[eb + e] - nb;
        atomicAdd(&sh_cnt[d], 1);
        atomicAdd(&sh_easum[d], ea[eb + e]);
    }
    __syncthreads();

    for (int p = wid; p < NODES * HEADS; p += 16) {
        int n = p >> 3, h = p & 7;
        const float* hr = sh_h + n * FDIM + h * CH;
        float v0 = hr[lane], v1 = hr[lane + 32];
        float s1 = v0 * sh_av[h * CH + lane] + v1 * sh_av[h * CH + lane + 32];
        float s2 = v0 * sh_av[512 + h * CH + lane] + v1 * sh_av[512 + h * CH + lane + 32];
#pragma unroll
        for (int o = 16; o > 0; o >>= 1) {
            s1 += __shfl_xor_sync(0xffffffffu, s1, o);
            s2 += __shfl_xor_sync(0xffffffffu, s2, o);
        }
        if (lane == 0) { sh_ssrc[p] = s1; sh_sdst[p] = s2; }
    }
    __syncthreads();

    if (tid == 0) {
        int o = 0;
        for (int n = 0; n < NODES; n++) { sh_off[n] = o; o += sh_cnt[n] + (LOOPS ? 1 : 0); }
    }
    __syncthreads();

    for (int e = tid; e < ECNT; e += 512) {
        int sl, dl; float eav;
        if (e < EPG) { sl = esrc[eb + e] - nb; dl = edst[eb + e] - nb; eav = ea[eb + e]; }
        else { sl = dl = e - EPG; eav = sh_easum[dl] / fmaxf((float)sh_cnt[dl], 1.f); }
        int pos = sh_off[dl] + atomicAdd(&sh_cur[dl], 1);
        sh_srcS[pos] = sl; sh_dstS[pos] = dl;
#pragma unroll
        for (int h = 0; h < 8; h++) {
            float al = sh_ssrc[sl * 8 + h] + sh_sdst[dl * 8 + h] + eav * sh_weae[h];
            al = al > 0.f ? al : 0.2f * al;
            sh_alS[pos * 8 + h] = al;
            atomicMax(&sh_amaxi[dl * 8 + h], __float_as_int(al));
        }
    }
    __syncthreads();

    for (int i = tid; i < ECNT; i += 512) {
        int dl = sh_dstS[i];
#pragma unroll
        for (int h = 0; h < 8; h++) {
            float p = expf(sh_alS[i * 8 + h] - __int_as_float(sh_amaxi[dl * 8 + h]));
            sh_alS[i * 8 + h] = p;
            atomicAdd(&sh_den[dl * 8 + h], p);
        }
    }
    __syncthreads();
    if (tid < 400) sh_den[tid] = 1.f / (sh_den[tid] + 1e-16f);
    __syncthreads();

    // aggregation: warp per node, float4 everywhere
    const int hh = lane >> 4;
    for (int n = wid; n < NODES; n += 16) {
        float4 a0 = {0,0,0,0}, a1 = {0,0,0,0}, a2 = {0,0,0,0}, a3 = {0,0,0,0};
        float dinv[8];
#pragma unroll
        for (int h = 0; h < 8; h++) dinv[h] = sh_den[n * 8 + h];
        const int beg = sh_off[n], end = beg + sh_cur[n];
        for (int j = beg; j < end; j++) {
            const int s = sh_srcS[j];
            const float4* hs4 = (const float4*)(sh_h + s * FDIM) + lane;
            float4 u = ((const float4*)(sh_alS + j * 8))[0];
            float4 v = ((const float4*)(sh_alS + j * 8))[1];
            float p0 = u.x * dinv[0], p1 = u.y * dinv[1];
            float p2 = u.z * dinv[2], p3 = u.w * dinv[3];
            float p4 = v.x * dinv[4], p5 = v.y * dinv[5];
            float p6 = v.z * dinv[6], p7 = v.w * dinv[7];
            float q0 = hh ? p1 : p0;
            float q1 = hh ? p3 : p2;
            float q2 = hh ? p5 : p4;
            float q3 = hh ? p7 : p6;
            float4 h0 = hs4[0], h1 = hs4[32], h2 = hs4[64], h3 = hs4[96];
            a0.x += q0*h0.x; a0.y += q0*h0.y; a0.z += q0*h0.z; a0.w += q0*h0.w;
            a1.x += q1*h1.x; a1.y += q1*h1.y; a1.z += q1*h1.z; a1.w += q1*h1.w;
            a2.x += q2*h2.x; a2.y += q2*h2.y; a2.z += q2*h2.z; a2.w += q2*h2.w;
            a3.x += q3*h3.x; a3.y += q3*h3.y; a3.z += q3*h3.z; a3.w += q3*h3.w;
        }
        float4* op = (float4*)(xout + (size_t)(nb + n) * FDIM) + lane;
        const float4* bp = (const float4*)bias + lane;
        float4 b;
        b = bp[0];
        a0.x = fmaxf(a0.x + b.x, 0.f); a0.y = fmaxf(a0.y + b.y, 0.f);
        a0.z = fmaxf(a0.z + b.z, 0.f); a0.w = fmaxf(a0.w + b.w, 0.f); op[0] = a0;
        b = bp[32];
        a1.x = fmaxf(a1.x + b.x, 0.f); a1.y = fmaxf(a1.y + b.y, 0.f);
        a1.z = fmaxf(a1.z + b.z, 0.f); a1.w = fmaxf(a1.w + b.w, 0.f); op[32] = a1;
        b = bp[64];
        a2.x = fmaxf(a2.x + b.x, 0.f); a2.y = fmaxf(a2.y + b.y, 0.f);
        a2.z = fmaxf(a2.z + b.z, 0.f); a2.w = fmaxf(a2.w + b.w, 0.f); op[64] = a2;
        b = bp[96];
        a3.x = fmaxf(a3.x + b.x, 0.f); a3.y = fmaxf(a3.y + b.y, 0.f);
        a3.z = fmaxf(a3.z + b.z, 0.f); a3.w = fmaxf(a3.w + b.w, 0.f); op[96] = a3;
    }
}

// ---------------- mean pool ----------------
__global__ void pool_k(const float* __restrict__ x3, float* __restrict__ gemb) {
    int b = blockIdx.x;
    int f = blockIdx.y * 128 + threadIdx.x;
    float s = 0.f;
#pragma unroll 10
    for (int n = 0; n < NODES; n++) s += x3[(size_t)(b * NODES + n) * FDIM + f];
    gemb[b * FDIM + f] = s * (1.f / 50.f);
}

// ---------------- build combined ----------------
__global__ void gather_k(const float* __restrict__ x3, const float* __restrict__ gemb,
                         float* __restrict__ comb) {
    int r = blockIdx.x;
    int b = r / 5, t = r - b * 5;
    for (int i = threadIdx.x; i < GRUI; i += 256)
        comb[(size_t)r * GRUI + i] =
            (i < 512) ? x3[(size_t)(b * NODES + t) * FDIM + i] : gemb[b * FDIM + i - 512];
}

// ---------------- GRU: GH = h @ Whh ----------------
__global__ void gru_gh_k(const float* __restrict__ h, const float* __restrict__ Whh,
                         float* __restrict__ GH) {
    __shared__ float hs[8 * GRUH];
    int b0 = blockIdx.x * 8;
    int tid = threadIdx.x;
    for (int i = tid; i < 8 * GRUH; i += 384) hs[i] = h[b0 * GRUH + i];
    __syncthreads();
    float acc[8];
#pragma unroll
    for (int r = 0; r < 8; r++) acc[r] = 0.f;
    for (int k = 0; k < GRUH; k++) {
        float w = Whh[k * G3 + tid];
#pragma unroll
        for (int r = 0; r < 8; r++) acc[r] += hs[r * GRUH + k] * w;
    }
#pragma unroll
    for (int r = 0; r < 8; r++) GH[(b0 + r) * G3 + tid] = acc[r];
}

// ---------------- GRU gate math ----------------
__global__ void gru_gate_k(const float* __restrict__ GI, int t,
                           const float* __restrict__ GHb, const float* __restrict__ hprev,
                           const float* __restrict__ bih, const float* __restrict__ bhh,
                           float* __restrict__ hnew, float* __restrict__ gout,
                           float* __restrict__ hlast) {
    int b = blockIdx.x, j = threadIdx.x;
    const float* gi = GI + (size_t)(b * NA + t) * G3;
    const float* gh = GHb + (size_t)b * G3;
    float ir = gi[j] + bih[j];
    float iz = gi[j + 128] + bih[j + 128];
    float in_ = gi[j + 256] + bih[j + 256];
    float hr = gh[j] + bhh[j];
    float hz = gh[j + 128] + bhh[j + 128];
    float hn = gh[j + 256] + bhh[j + 256];
    float r = 1.f / (1.f + expf(-(ir + hr)));
    float z = 1.f / (1.f + expf(-(iz + hz)));
    float nn = tanhf(in_ + r * hn);
    float hp = hprev[b * GRUH + j];
    float h = (1.f - z) * nn + z * hp;
    hnew[b * GRUH + j] = h;
    gout[(size_t)(b * NA + t) * GRUH + j] = h;
    if (hlast) hlast[b * GRUH + j] = h;
}

// ---------------- FC head ----------------
__global__ void fc_k(const float* __restrict__ gout, const float* __restrict__ W1,
                     const float* __restrict__ b1, const float* __restrict__ W2,
                     const float* __restrict__ b2, const float* __restrict__ ls,
                     float* __restrict__ out) {
    __shared__ float g[128];
    __shared__ float f1[64];
    int r = blockIdx.x, tid = threadIdx.x;
    g[tid] = gout[(size_t)r * GRUH + tid];
    g[tid + 64] = gout[(size_t)r * GRUH + tid + 64];
    __syncthreads();
    float acc = b1[tid];
#pragma unroll 8
    for (int k = 0; k < 128; k++) acc += g[k] * W1[k * 64 + tid];
    f1[tid] = acc > 0.f ? acc : 0.f;
    __syncthreads();
    if (tid < 3) {
        float a2 = b2[tid];
#pragma unroll
        for (int k = 0; k < 64; k++) a2 += f1[k] * W2[k * 3 + tid];
        out[r * 3 + tid] = a2;
        float l = ls[tid];
        l = fminf(fmaxf(l, -20.f), 2.f);
        out[NGRAPH * NA * 3 + r * 3 + tid] = expf(l);
    }
}

// ---------------- launch ----------------
extern "C" void kernel_launch(void* const* d_in, const int* in_sizes, int n_in,
                              void* d_out, int out_size) {
    const float* x      = (const float*)d_in[0];
    const int*   ei     = (const int*)d_in[1];
    const float* ea     = (const float*)d_in[2];
    const float* hid0   = (const float*)d_in[3];
    const float* W1     = (const float*)d_in[4];
    const float* a_s1   = (const float*)d_in[5];
    const float* a_d1   = (const float*)d_in[6];
    const float* We1    = (const float*)d_in[7];
    const float* ae1    = (const float*)d_in[8];
    const float* b1     = (const float*)d_in[9];
    const float* W2     = (const float*)d_in[10];
    const float* a_s2   = (const float*)d_in[11];
    const float* a_d2   = (const float*)d_in[12];
    const float* We2    = (const float*)d_in[13];
    const float* ae2    = (const float*)d_in[14];
    const float* b2     = (const float*)d_in[15];
    const float* W3     = (const float*)d_in[16];
    const float* a_s3   = (const float*)d_in[17];
    const float* a_d3   = (const float*)d_in[18];
    const float* We3    = (const float*)d_in[19];
    const float* ae3    = (const float*)d_in[20];
    const float* b3     = (const float*)d_in[21];
    const float* Wih    = (const float*)d_in[22];
    const float* Whh    = (const float*)d_in[23];
    const float* bih    = (const float*)d_in[24];
    const float* bhh    = (const float*)d_in[25];
    const float* fc1W   = (const float*)d_in[26];
    const float* fc1b   = (const float*)d_in[27];
    const float* fc2W   = (const float*)d_in[28];
    const float* fc2b   = (const float*)d_in[29];
    const float* logstd = (const float*)d_in[30];
    float* out = (float*)d_out;

    float *bufA, *bufB, *gemb, *comb, *GI, *GHb, *h0b, *h1b, *gout;
    __nv_bfloat16 *Ah, *Al, *Bh, *Bl;
    cudaGetSymbolAddress((void**)&bufA, g_bufA);
    cudaGetSymbolAddress((void**)&bufB, g_bufB);
    cudaGetSymbolAddress((void**)&gemb, g_gemb);
    cudaGetSymbolAddress((void**)&comb, g_comb);
    cudaGetSymbolAddress((void**)&GI,   g_GI);
    cudaGetSymbolAddress((void**)&GHb,  g_GHbuf);
    cudaGetSymbolAddress((void**)&h0b,  g_h0);
    cudaGetSymbolAddress((void**)&h1b,  g_h1);
    cudaGetSymbolAddress((void**)&gout, g_gruout);
    cudaGetSymbolAddress((void**)&Ah, g_Ah);
    cudaGetSymbolAddress((void**)&Al, g_Al);
    cudaGetSymbolAddress((void**)&Bh, g_Bh);
    cudaGetSymbolAddress((void**)&Bl, g_Bl);

    cudaFuncSetAttribute(gat_kernel<false>, cudaFuncAttributeMaxDynamicSharedMemorySize, GAT_SMEM_BYTES);
    cudaFuncSetAttribute(gat_kernel<true>,  cudaFuncAttributeMaxDynamicSharedMemorySize, GAT_SMEM_BYTES);
    cudaFuncSetAttribute(gemm_mma, cudaFuncAttributeMaxDynamicSharedMemorySize, GEMM_SMEM);

    const int* esrc = ei;
    const int* edst = ei + NE;

    // layer 1
    lin1_k<<<(NN * FDIM) / 256, 256>>>(x, W1, bufA);
    gat_kernel<false><<<NGRAPH, 512, GAT_SMEM_BYTES>>>(bufA, esrc, edst, ea,
                                                       a_s1, a_d1, We1, ae1, b1, bufB);
    // layer 2: x1 @ W2 via HMMA bf16-split
    splitT_k<<<(FDIM * FDIM + 255) / 256, 256>>>(W2, Bh, Bl, FDIM, FDIM);
    split_k<<<(NN * FDIM / 4 + 255) / 256, 256>>>(bufB, Ah, Al, NN * FDIM / 4);
    gemm_mma<<<dim3(FDIM / 128, NN / 128), 256, GEMM_SMEM>>>(Ah, Al, Bh, Bl, bufA,
                                                             NN, FDIM, FDIM);
    gat_kernel<true><<<NGRAPH, 512, GAT_SMEM_BYTES>>>(bufA, esrc, edst, ea,
                                                      a_s2, a_d2, We2, ae2, b2, bufB);
    // layer 3
    splitT_k<<<(FDIM * FDIM + 255) / 256, 256>>>(W3, Bh, Bl, FDIM, FDIM);
    split_k<<<(NN * FDIM / 4 + 255) / 256, 256>>>(bufB, Ah, Al, NN * FDIM / 4);
    gemm_mma<<<dim3(FDIM / 128, NN / 128), 256, GEMM_SMEM>>>(Ah, Al, Bh, Bl, bufA,
                                                             NN, FDIM, FDIM);
    gat_kernel<true><<<NGRAPH, 512, GAT_SMEM_BYTES>>>(bufA, esrc, edst, ea,
                                                      a_s3, a_d3, We3, ae3, b3, bufB);
    // pooling + GRU input GEMM
    pool_k<<<dim3(NGRAPH, FDIM / 128), 128>>>(bufB, gemb);
    gather_k<<<NGRAPH * NA, 256>>>(bufB, gemb, comb);
    splitT_k<<<(GRUI * G3 + 255) / 256, 256>>>(Wih, Bh, Bl, GRUI, G3);
    split_k<<<(NGRAPH * NA * GRUI / 4 + 255) / 256, 256>>>(comb, Ah, Al,
                                                           NGRAPH * NA * GRUI / 4);
    gemm_mma<<<dim3(G3 / 128, (NGRAPH * NA) / 128), 256, GEMM_SMEM>>>(
        Ah, Al, Bh, Bl, GI, NGRAPH * NA, G3, GRUI);
    // GRU recurrence
    cudaMemcpyAsync(h0b, hid0, (size_t)NGRAPH * GRUH * sizeof(float),
                    cudaMemcpyDeviceToDevice);
    for (int t = 0; t < NA; t++) {
        float* hc = (t & 1) ? h1b : h0b;
        float* hn = (t & 1) ? h0b : h1b;
        gru_gh_k<<<NGRAPH / 8, G3>>>(hc, Whh, GHb);
        gru_gate_k<<<NGRAPH, GRUH>>>(GI, t, GHb, hc, bih, bhh, hn, gout,
                                     (t == NA - 1) ? (out + NGRAPH * NA * 3 * 2) : nullptr);
    }
    fc_k<<<NGRAPH * NA, 64>>>(gout, fc1W, fc1b, fc2W, fc2b, logstd, out);
}